// round 15
// baseline (speedup 1.0000x reference)
#include <cuda_runtime.h>
#include <cuda_bf16.h>
#include <stdint.h>

#define NSEQ 384
#define NTOK 147456            // 384*384
#define CDIM 128
#define SROW 136               // smem row stride in bf16 elements (conflict-free)
#define LN_EPS 1e-5f

// ---------------- scratch (device globals: allocation-free) ----------------
__device__ __align__(16) __nv_bfloat16 g_ah[(size_t)CDIM * NTOK];
__device__ __align__(16) __nv_bfloat16 g_al[(size_t)CDIM * NTOK];
__device__ __align__(16) __nv_bfloat16 g_bh[(size_t)CDIM * NTOK];
__device__ __align__(16) __nv_bfloat16 g_bl[(size_t)CDIM * NTOK];
__device__ __align__(16) float         g_gate[(size_t)CDIM * NTOK];
__device__ __align__(16) float         g_o[(size_t)CDIM * NTOK];
__device__ __align__(16) __nv_bfloat16 g_wh[6 * 16384];
__device__ __align__(16) __nv_bfloat16 g_wl[6 * 16384];

// ---------------- helpers ----------------
__device__ __forceinline__ uint32_t ld32(const __nv_bfloat16* p) {
    return *(const uint32_t*)p;
}

__device__ __forceinline__ void mma16816(float* c, const uint32_t* a, const uint32_t* b) {
    asm volatile(
        "mma.sync.aligned.m16n8k16.row.col.f32.bf16.bf16.f32 "
        "{%0,%1,%2,%3}, {%4,%5,%6,%7}, {%8,%9}, {%0,%1,%2,%3};\n"
        : "+f"(c[0]), "+f"(c[1]), "+f"(c[2]), "+f"(c[3])
        : "r"(a[0]), "r"(a[1]), "r"(a[2]), "r"(a[3]), "r"(b[0]), "r"(b[1]));
}

__device__ __forceinline__ float sigm(float x) { return 1.0f / (1.0f + __expf(-x)); }

__device__ __forceinline__ void store_split2(__nv_bfloat16* H, __nv_bfloat16* L,
                                             size_t off, float v0, float v1) {
    __nv_bfloat16 h0 = __float2bfloat16(v0);
    __nv_bfloat16 h1 = __float2bfloat16(v1);
    __nv_bfloat16 l0 = __float2bfloat16(v0 - __bfloat162float(h0));
    __nv_bfloat16 l1 = __float2bfloat16(v1 - __bfloat162float(h1));
    __nv_bfloat162 hh; hh.x = h0; hh.y = h1;
    __nv_bfloat162 ll; ll.x = l0; ll.y = l1;
    *(__nv_bfloat162*)(H + off) = hh;
    *(__nv_bfloat162*)(L + off) = ll;
}

// 128xN(=128) x K(=nk*16) GEMM micro-kernel. A: [m(128) x k] rows, stride SROW.
// B: [n(128) x k] rows (i.e. col-major k-major), stride SROW. bf16x3 split.
// Warp computes a 64x32 tile at (wm, wn). acc[4][4][4] fp32.
__device__ __forceinline__ void gemm_tile(
    const __nv_bfloat16* __restrict__ Ah, const __nv_bfloat16* __restrict__ Al,
    const __nv_bfloat16* __restrict__ Bh, const __nv_bfloat16* __restrict__ Bl,
    float acc[4][4][4], int g, int tig, int wm, int wn, int nk)
{
    for (int ks = 0; ks < nk; ++ks) {
        uint32_t ra_h[4][4], ra_l[4][4], rb_h[4][2], rb_l[4][2];
        int k0 = ks * 16 + tig * 2;
#pragma unroll
        for (int mi = 0; mi < 4; ++mi) {
            int row = wm + mi * 16 + g;
            const __nv_bfloat16* ph = Ah + row * SROW + k0;
            const __nv_bfloat16* pl = Al + row * SROW + k0;
            ra_h[mi][0] = ld32(ph);            ra_h[mi][1] = ld32(ph + 8 * SROW);
            ra_h[mi][2] = ld32(ph + 8);        ra_h[mi][3] = ld32(ph + 8 * SROW + 8);
            ra_l[mi][0] = ld32(pl);            ra_l[mi][1] = ld32(pl + 8 * SROW);
            ra_l[mi][2] = ld32(pl + 8);        ra_l[mi][3] = ld32(pl + 8 * SROW + 8);
        }
#pragma unroll
        for (int ni = 0; ni < 4; ++ni) {
            int row = wn + ni * 8 + g;
            const __nv_bfloat16* ph = Bh + row * SROW + k0;
            const __nv_bfloat16* pl = Bl + row * SROW + k0;
            rb_h[ni][0] = ld32(ph);  rb_h[ni][1] = ld32(ph + 8);
            rb_l[ni][0] = ld32(pl);  rb_l[ni][1] = ld32(pl + 8);
        }
        // pass-major ordering: 16 independent MMAs per pass hide MMA latency
#pragma unroll
        for (int mi = 0; mi < 4; ++mi)
#pragma unroll
            for (int ni = 0; ni < 4; ++ni)
                mma16816(acc[mi][ni], ra_h[mi], rb_h[ni]);
#pragma unroll
        for (int mi = 0; mi < 4; ++mi)
#pragma unroll
            for (int ni = 0; ni < 4; ++ni)
                mma16816(acc[mi][ni], ra_h[mi], rb_l[ni]);
#pragma unroll
        for (int mi = 0; mi < 4; ++mi)
#pragma unroll
            for (int ni = 0; ni < 4; ++ni)
                mma16816(acc[mi][ni], ra_l[mi], rb_h[ni]);
    }
}

__device__ __forceinline__ void zero_acc(float acc[4][4][4]) {
#pragma unroll
    for (int mi = 0; mi < 4; ++mi)
#pragma unroll
        for (int ni = 0; ni < 4; ++ni)
#pragma unroll
            for (int u = 0; u < 4; ++u) acc[mi][ni][u] = 0.0f;
}

// load one prepped 128x128 weight (hi+lo) into smem tiles with SROW stride
__device__ __forceinline__ void load_weight_smem(int p, int tid,
                                                 __nv_bfloat16* wh, __nv_bfloat16* wl) {
    const __nv_bfloat16* sh = g_wh + p * 16384;
    const __nv_bfloat16* sl = g_wl + p * 16384;
#pragma unroll
    for (int it = 0; it < 8; ++it) {
        int h = it * 2048 + tid * 8;
        int r = h >> 7, kk = h & 127;
        *(uint4*)(wh + r * SROW + kk) = *(const uint4*)(sh + h);
        *(uint4*)(wl + r * SROW + kk) = *(const uint4*)(sl + h);
    }
}

// ---------------- kernel 1: weight prep (split + transpose) ----------------
__global__ void k_prep(const float* Wa, const float* Wga, const float* Wb,
                       const float* Wgb, const float* Wg, const float* Wo) {
    int idx = blockIdx.x * 256 + threadIdx.x;   // 0 .. 6*16384-1
    const float* srcs[6] = {Wa, Wga, Wb, Wgb, Wg, Wo};
    int w = idx >> 14;
    int r = idx & 16383;
    int m = r >> 7;    // output channel
    int k = r & 127;   // input channel
    float v = srcs[w][k * 128 + m];   // transposed: Wt[m][k] = W[k][m]
    __nv_bfloat16 hi = __float2bfloat16(v);
    __nv_bfloat16 lo = __float2bfloat16(v - __bfloat162float(hi));
    g_wh[idx] = hi;
    g_wl[idx] = lo;
}

// ---------------- kernel 2: LN1 + 5 projections ----------------
__global__ void __launch_bounds__(256, 1) k_proj(
    const float* __restrict__ z,
    const float* __restrict__ g1, const float* __restrict__ b1,
    const float* __restrict__ ba, const float* __restrict__ bga,
    const float* __restrict__ bb, const float* __restrict__ bgb,
    const float* __restrict__ bg)
{
    extern __shared__ __nv_bfloat16 sm[];
    __nv_bfloat16* znh = sm;
    __nv_bfloat16* znl = sm + 128 * SROW;
    __nv_bfloat16* wh  = sm + 2 * 128 * SROW;
    __nv_bfloat16* wl  = sm + 3 * 128 * SROW;

    int tid = threadIdx.x, lane = tid & 31, warp = tid >> 5;
    int g = lane >> 2, tig = lane & 3;
    int wm = (warp >> 2) * 64;      // channel offset
    int wn = (warp & 3) * 32;       // token offset
    size_t t0 = (size_t)blockIdx.x * 128;

    // ---- LN1: each warp handles 16 token rows ----
    float gv[4], bv[4];
#pragma unroll
    for (int u = 0; u < 4; ++u) { gv[u] = g1[lane + 32 * u]; bv[u] = b1[lane + 32 * u]; }
    for (int rr = 0; rr < 16; ++rr) {
        int r = warp * 16 + rr;
        const float* zr = z + (t0 + r) * 128;
        float x[4], s = 0.f, ss = 0.f;
#pragma unroll
        for (int u = 0; u < 4; ++u) { x[u] = zr[lane + 32 * u]; s += x[u]; ss += x[u] * x[u]; }
#pragma unroll
        for (int o = 16; o > 0; o >>= 1) {
            s  += __shfl_xor_sync(0xFFFFFFFFu, s, o);
            ss += __shfl_xor_sync(0xFFFFFFFFu, ss, o);
        }
        float mean = s * (1.0f / 128.0f);
        float var  = ss * (1.0f / 128.0f) - mean * mean;
        float rstd = rsqrtf(var + LN_EPS);
#pragma unroll
        for (int u = 0; u < 4; ++u) {
            float v = (x[u] - mean) * rstd * gv[u] + bv[u];
            __nv_bfloat16 hi = __float2bfloat16(v);
            __nv_bfloat16 lo = __float2bfloat16(v - __bfloat162float(hi));
            znh[r * SROW + lane + 32 * u] = hi;
            znl[r * SROW + lane + 32 * u] = lo;
        }
    }

    float acc[4][4][4];
    float sva[4][4][4];

    // ---- P0: zn @ Wa + ba -> sva ----
    load_weight_smem(0, tid, wh, wl);
    __syncthreads();
    zero_acc(acc);
    gemm_tile(wh, wl, znh, znl, acc, g, tig, wm, wn, 8);
#pragma unroll
    for (int mi = 0; mi < 4; ++mi) {
        int c0 = wm + mi * 16 + g;
        float bz0 = ba[c0], bz1 = ba[c0 + 8];
#pragma unroll
        for (int ni = 0; ni < 4; ++ni) {
            sva[mi][ni][0] = acc[mi][ni][0] + bz0;
            sva[mi][ni][1] = acc[mi][ni][1] + bz0;
            sva[mi][ni][2] = acc[mi][ni][2] + bz1;
            sva[mi][ni][3] = acc[mi][ni][3] + bz1;
        }
    }

    // ---- P1: zn @ Wga + bga; a = sva * sigmoid(.) -> g_ah/g_al (channel-major) ----
    __syncthreads();
    load_weight_smem(1, tid, wh, wl);
    __syncthreads();
    zero_acc(acc);
    gemm_tile(wh, wl, znh, znl, acc, g, tig, wm, wn, 8);
#pragma unroll
    for (int mi = 0; mi < 4; ++mi) {
        int c0 = wm + mi * 16 + g, c1 = c0 + 8;
        float q0 = bga[c0], q1 = bga[c1];
#pragma unroll
        for (int ni = 0; ni < 4; ++ni) {
            size_t t = t0 + wn + ni * 8 + tig * 2;
            float v00 = sva[mi][ni][0] * sigm(acc[mi][ni][0] + q0);
            float v01 = sva[mi][ni][1] * sigm(acc[mi][ni][1] + q0);
            float v10 = sva[mi][ni][2] * sigm(acc[mi][ni][2] + q1);
            float v11 = sva[mi][ni][3] * sigm(acc[mi][ni][3] + q1);
            store_split2(g_ah, g_al, (size_t)c0 * NTOK + t, v00, v01);
            store_split2(g_ah, g_al, (size_t)c1 * NTOK + t, v10, v11);
        }
    }

    // ---- P2: zn @ Wb + bb -> sva ----
    __syncthreads();
    load_weight_smem(2, tid, wh, wl);
    __syncthreads();
    zero_acc(acc);
    gemm_tile(wh, wl, znh, znl, acc, g, tig, wm, wn, 8);
#pragma unroll
    for (int mi = 0; mi < 4; ++mi) {
        int c0 = wm + mi * 16 + g;
        float bz0 = bb[c0], bz1 = bb[c0 + 8];
#pragma unroll
        for (int ni = 0; ni < 4; ++ni) {
            sva[mi][ni][0] = acc[mi][ni][0] + bz0;
            sva[mi][ni][1] = acc[mi][ni][1] + bz0;
            sva[mi][ni][2] = acc[mi][ni][2] + bz1;
            sva[mi][ni][3] = acc[mi][ni][3] + bz1;
        }
    }

    // ---- P3: zn @ Wgb + bgb; b = sva * sigmoid(.) -> g_bh/g_bl ----
    __syncthreads();
    load_weight_smem(3, tid, wh, wl);
    __syncthreads();
    zero_acc(acc);
    gemm_tile(wh, wl, znh, znl, acc, g, tig, wm, wn, 8);
#pragma unroll
    for (int mi = 0; mi < 4; ++mi) {
        int c0 = wm + mi * 16 + g, c1 = c0 + 8;
        float q0 = bgb[c0], q1 = bgb[c1];
#pragma unroll
        for (int ni = 0; ni < 4; ++ni) {
            size_t t = t0 + wn + ni * 8 + tig * 2;
            float v00 = sva[mi][ni][0] * sigm(acc[mi][ni][0] + q0);
            float v01 = sva[mi][ni][1] * sigm(acc[mi][ni][1] + q0);
            float v10 = sva[mi][ni][2] * sigm(acc[mi][ni][2] + q1);
            float v11 = sva[mi][ni][3] * sigm(acc[mi][ni][3] + q1);
            store_split2(g_bh, g_bl, (size_t)c0 * NTOK + t, v00, v01);
            store_split2(g_bh, g_bl, (size_t)c1 * NTOK + t, v10, v11);
        }
    }

    // ---- P4: gate = sigmoid(zn @ Wg + bg) -> g_gate (channel-major fp32) ----
    __syncthreads();
    load_weight_smem(4, tid, wh, wl);
    __syncthreads();
    zero_acc(acc);
    gemm_tile(wh, wl, znh, znl, acc, g, tig, wm, wn, 8);
#pragma unroll
    for (int mi = 0; mi < 4; ++mi) {
        int c0 = wm + mi * 16 + g, c1 = c0 + 8;
        float q0 = bg[c0], q1 = bg[c1];
#pragma unroll
        for (int ni = 0; ni < 4; ++ni) {
            size_t t = t0 + wn + ni * 8 + tig * 2;
            float2 v0 = make_float2(sigm(acc[mi][ni][0] + q0), sigm(acc[mi][ni][1] + q0));
            float2 v1 = make_float2(sigm(acc[mi][ni][2] + q1), sigm(acc[mi][ni][3] + q1));
            *(float2*)(g_gate + (size_t)c0 * NTOK + t) = v0;
            *(float2*)(g_gate + (size_t)c1 * NTOK + t) = v1;
        }
    }
}

// ---------------- kernel 3: triangle einsum (per-channel GEMM A @ B^T) ----------------
__global__ void __launch_bounds__(256, 1) k_tri()
{
    extern __shared__ __nv_bfloat16 sm[];
    __nv_bfloat16* ah = sm;
    __nv_bfloat16* al = sm + 128 * SROW;
    __nv_bfloat16* bh = sm + 2 * 128 * SROW;
    __nv_bfloat16* bl = sm + 3 * 128 * SROW;

    int tid = threadIdx.x, lane = tid & 31, warp = tid >> 5;
    int g = lane >> 2, tig = lane & 3;
    int wm = (warp >> 2) * 64;
    int wn = (warp & 3) * 32;

    int c    = blockIdx.x / 9;     // tile index fastest -> same-c blocks co-resident
    int tile = blockIdx.x % 9;
    int i0 = (tile / 3) * 128;
    int j0 = (tile % 3) * 128;
    size_t baseA = (size_t)c * NTOK + (size_t)i0 * NSEQ;
    size_t baseB = (size_t)c * NTOK + (size_t)j0 * NSEQ;

    float acc[4][4][4];
    zero_acc(acc);

    for (int kc = 0; kc < 3; ++kc) {
#pragma unroll
        for (int it = 0; it < 8; ++it) {
            int h = it * 2048 + tid * 8;
            int r = h >> 7, kk = h & 127;
            size_t ga = baseA + (size_t)r * NSEQ + kc * 128 + kk;
            size_t gb = baseB + (size_t)r * NSEQ + kc * 128 + kk;
            *(uint4*)(ah + r * SROW + kk) = *(const uint4*)(g_ah + ga);
            *(uint4*)(al + r * SROW + kk) = *(const uint4*)(g_al + ga);
            *(uint4*)(bh + r * SROW + kk) = *(const uint4*)(g_bh + gb);
            *(uint4*)(bl + r * SROW + kk) = *(const uint4*)(g_bl + gb);
        }
        __syncthreads();
        gemm_tile(ah, al, bh, bl, acc, g, tig, wm, wn, 8);
        __syncthreads();
    }

    // write o channel-major fp32
#pragma unroll
    for (int mi = 0; mi < 4; ++mi) {
#pragma unroll
        for (int ni = 0; ni < 4; ++ni) {
            int r0  = i0 + wm + mi * 16 + g;
            int col = j0 + wn + ni * 8 + tig * 2;
            size_t off = (size_t)c * NTOK + (size_t)r0 * NSEQ + col;
            *(float2*)(g_o + off)            = make_float2(acc[mi][ni][0], acc[mi][ni][1]);
            *(float2*)(g_o + off + 8 * NSEQ) = make_float2(acc[mi][ni][2], acc[mi][ni][3]);
        }
    }
}

// ---------------- kernel 4: gather + LN2 + @Wo + gate ----------------
__global__ void __launch_bounds__(256, 1) k_out(
    const float* __restrict__ g2, const float* __restrict__ b2,
    const float* __restrict__ bo, float* __restrict__ out)
{
    extern __shared__ char smraw[];
    float* ot = (float*)smraw;                                      // 128 x 129 fp32
    __nv_bfloat16* onh = (__nv_bfloat16*)(smraw + 128 * 129 * 4);
    __nv_bfloat16* onl = onh + 128 * SROW;
    __nv_bfloat16* wh  = onl + 128 * SROW;
    __nv_bfloat16* wl  = wh + 128 * SROW;

    int tid = threadIdx.x, lane = tid & 31, warp = tid >> 5;
    int g = lane >> 2, tig = lane & 3;
    int wm = (warp >> 2) * 64;
    int wn = (warp & 3) * 32;
    size_t t0 = (size_t)blockIdx.x * 128;

    // gather o[c][t0..t0+127] -> ot[t][c] (coalesced reads, conflict-free smem writes)
#pragma unroll
    for (int it = 0; it < 64; ++it) {
        int idx = it * 256 + tid;
        int c  = idx >> 7;
        int tt = idx & 127;
        ot[tt * 129 + c] = g_o[(size_t)c * NTOK + t0 + tt];
    }
    __syncthreads();

    // LN2 per token row
    float gv[4], bv[4];
#pragma unroll
    for (int u = 0; u < 4; ++u) { gv[u] = g2[lane + 32 * u]; bv[u] = b2[lane + 32 * u]; }
    for (int rr = 0; rr < 16; ++rr) {
        int r = warp * 16 + rr;
        float x[4], s = 0.f, ss = 0.f;
#pragma unroll
        for (int u = 0; u < 4; ++u) {
            x[u] = ot[r * 129 + lane + 32 * u];
            s += x[u]; ss += x[u] * x[u];
        }
#pragma unroll
        for (int o = 16; o > 0; o >>= 1) {
            s  += __shfl_xor_sync(0xFFFFFFFFu, s, o);
            ss += __shfl_xor_sync(0xFFFFFFFFu, ss, o);
        }
        float mean = s * (1.0f / 128.0f);
        float var  = ss * (1.0f / 128.0f) - mean * mean;
        float rstd = rsqrtf(var + LN_EPS);
#pragma unroll
        for (int u = 0; u < 4; ++u) {
            float v = (x[u] - mean) * rstd * gv[u] + bv[u];
            __nv_bfloat16 hi = __float2bfloat16(v);
            __nv_bfloat16 lo = __float2bfloat16(v - __bfloat162float(hi));
            onh[r * SROW + lane + 32 * u] = hi;
            onl[r * SROW + lane + 32 * u] = lo;
        }
    }

    load_weight_smem(5, tid, wh, wl);   // Wo
    __syncthreads();

    float acc[4][4][4];
    zero_acc(acc);
    gemm_tile(wh, wl, onh, onl, acc, g, tig, wm, wn, 8);

    // epilogue: out[t][c] = gate[c][t] * (acc + bo[c])
#pragma unroll
    for (int mi = 0; mi < 4; ++mi) {
        int c0 = wm + mi * 16 + g, c1 = c0 + 8;
        float q0 = bo[c0], q1 = bo[c1];
#pragma unroll
        for (int ni = 0; ni < 4; ++ni) {
            size_t t = t0 + wn + ni * 8 + tig * 2;
            float2 gt0 = *(const float2*)(g_gate + (size_t)c0 * NTOK + t);
            float2 gt1 = *(const float2*)(g_gate + (size_t)c1 * NTOK + t);
            out[t * 128 + c0]       = gt0.x * (acc[mi][ni][0] + q0);
            out[(t + 1) * 128 + c0] = gt0.y * (acc[mi][ni][1] + q0);
            out[t * 128 + c1]       = gt1.x * (acc[mi][ni][2] + q1);
            out[(t + 1) * 128 + c1] = gt1.y * (acc[mi][ni][3] + q1);
        }
    }
}

// ---------------- launch ----------------
extern "C" void kernel_launch(void* const* d_in, const int* in_sizes, int n_in,
                              void* d_out, int out_size)
{
    const float* z    = (const float*)d_in[0];
    const float* ln1g = (const float*)d_in[1];
    const float* ln1b = (const float*)d_in[2];
    const float* ln2g = (const float*)d_in[3];
    const float* ln2b = (const float*)d_in[4];
    const float* Wa   = (const float*)d_in[5];
    const float* ba   = (const float*)d_in[6];
    const float* Wga  = (const float*)d_in[7];
    const float* bga  = (const float*)d_in[8];
    const float* Wb   = (const float*)d_in[9];
    const float* bb   = (const float*)d_in[10];
    const float* Wgb  = (const float*)d_in[11];
    const float* bgb  = (const float*)d_in[12];
    const float* Wg   = (const float*)d_in[13];
    const float* bg   = (const float*)d_in[14];
    const float* Wo   = (const float*)d_in[15];
    const float* bo   = (const float*)d_in[16];

    const int smA = 4 * 128 * SROW * 2;                 // 139264 B
    const int smO = 128 * 129 * 4 + 4 * 128 * SROW * 2; // 205312 B
    cudaFuncSetAttribute(k_proj, cudaFuncAttributeMaxDynamicSharedMemorySize, smA);
    cudaFuncSetAttribute(k_tri,  cudaFuncAttributeMaxDynamicSharedMemorySize, smA);
    cudaFuncSetAttribute(k_out,  cudaFuncAttributeMaxDynamicSharedMemorySize, smO);

    k_prep<<<384, 256>>>(Wa, Wga, Wb, Wgb, Wg, Wo);
    k_proj<<<1152, 256, smA>>>(z, ln1g, ln1b, ba, bga, bb, bgb, bg);
    k_tri<<<1152, 256, smA>>>();
    k_out<<<1152, 256, smO>>>(ln2g, ln2b, bo, (float*)d_out);
}

// round 16
// speedup vs baseline: 1.0015x; 1.0015x over previous
#include <cuda_runtime.h>
#include <cuda_bf16.h>
#include <stdint.h>

#define NSEQ 384
#define NTOK 147456            // 384*384
#define CDIM 128
#define SROW 136               // smem row stride in bf16 elements (conflict-free)
#define LN_EPS 1e-5f

// ---------------- scratch (device globals: allocation-free) ----------------
__device__ __align__(16) __nv_bfloat16 g_ah[(size_t)CDIM * NTOK];
__device__ __align__(16) __nv_bfloat16 g_al[(size_t)CDIM * NTOK];
__device__ __align__(16) __nv_bfloat16 g_bh[(size_t)CDIM * NTOK];
__device__ __align__(16) __nv_bfloat16 g_bl[(size_t)CDIM * NTOK];
__device__ __align__(16) float         g_gate[(size_t)CDIM * NTOK];
__device__ __align__(16) float         g_o[(size_t)CDIM * NTOK];
__device__ __align__(16) __nv_bfloat16 g_wh[6 * 16384];
__device__ __align__(16) __nv_bfloat16 g_wl[6 * 16384];

// ---------------- helpers ----------------
__device__ __forceinline__ uint32_t ld32(const __nv_bfloat16* p) {
    return *(const uint32_t*)p;
}

__device__ __forceinline__ void mma16816(float* c, const uint32_t* a, const uint32_t* b) {
    asm volatile(
        "mma.sync.aligned.m16n8k16.row.col.f32.bf16.bf16.f32 "
        "{%0,%1,%2,%3}, {%4,%5,%6,%7}, {%8,%9}, {%0,%1,%2,%3};\n"
        : "+f"(c[0]), "+f"(c[1]), "+f"(c[2]), "+f"(c[3])
        : "r"(a[0]), "r"(a[1]), "r"(a[2]), "r"(a[3]), "r"(b[0]), "r"(b[1]));
}

__device__ __forceinline__ float sigm(float x) { return 1.0f / (1.0f + __expf(-x)); }

__device__ __forceinline__ void store_split2(__nv_bfloat16* H, __nv_bfloat16* L,
                                             size_t off, float v0, float v1) {
    __nv_bfloat16 h0 = __float2bfloat16(v0);
    __nv_bfloat16 h1 = __float2bfloat16(v1);
    __nv_bfloat16 l0 = __float2bfloat16(v0 - __bfloat162float(h0));
    __nv_bfloat16 l1 = __float2bfloat16(v1 - __bfloat162float(h1));
    __nv_bfloat162 hh; hh.x = h0; hh.y = h1;
    __nv_bfloat162 ll; ll.x = l0; ll.y = l1;
    *(__nv_bfloat162*)(H + off) = hh;
    *(__nv_bfloat162*)(L + off) = ll;
}

// 128xN(=128) x K(=nk*16) GEMM micro-kernel. A: [m(128) x k] rows, stride SROW.
// B: [n(128) x k] rows (i.e. col-major k-major), stride SROW. bf16x3 split.
// Warp computes a 64x32 tile at (wm, wn). acc[4][4][4] fp32.
__device__ __forceinline__ void gemm_tile(
    const __nv_bfloat16* __restrict__ Ah, const __nv_bfloat16* __restrict__ Al,
    const __nv_bfloat16* __restrict__ Bh, const __nv_bfloat16* __restrict__ Bl,
    float acc[4][4][4], int g, int tig, int wm, int wn, int nk)
{
    for (int ks = 0; ks < nk; ++ks) {
        uint32_t ra_h[4][4], ra_l[4][4], rb_h[4][2], rb_l[4][2];
        int k0 = ks * 16 + tig * 2;
#pragma unroll
        for (int mi = 0; mi < 4; ++mi) {
            int row = wm + mi * 16 + g;
            const __nv_bfloat16* ph = Ah + row * SROW + k0;
            const __nv_bfloat16* pl = Al + row * SROW + k0;
            ra_h[mi][0] = ld32(ph);            ra_h[mi][1] = ld32(ph + 8 * SROW);
            ra_h[mi][2] = ld32(ph + 8);        ra_h[mi][3] = ld32(ph + 8 * SROW + 8);
            ra_l[mi][0] = ld32(pl);            ra_l[mi][1] = ld32(pl + 8 * SROW);
            ra_l[mi][2] = ld32(pl + 8);        ra_l[mi][3] = ld32(pl + 8 * SROW + 8);
        }
#pragma unroll
        for (int ni = 0; ni < 4; ++ni) {
            int row = wn + ni * 8 + g;
            const __nv_bfloat16* ph = Bh + row * SROW + k0;
            const __nv_bfloat16* pl = Bl + row * SROW + k0;
            rb_h[ni][0] = ld32(ph);  rb_h[ni][1] = ld32(ph + 8);
            rb_l[ni][0] = ld32(pl);  rb_l[ni][1] = ld32(pl + 8);
        }
        // pass-major ordering: 16 independent MMAs per pass hide MMA latency
#pragma unroll
        for (int mi = 0; mi < 4; ++mi)
#pragma unroll
            for (int ni = 0; ni < 4; ++ni)
                mma16816(acc[mi][ni], ra_h[mi], rb_h[ni]);
#pragma unroll
        for (int mi = 0; mi < 4; ++mi)
#pragma unroll
            for (int ni = 0; ni < 4; ++ni)
                mma16816(acc[mi][ni], ra_h[mi], rb_l[ni]);
#pragma unroll
        for (int mi = 0; mi < 4; ++mi)
#pragma unroll
            for (int ni = 0; ni < 4; ++ni)
                mma16816(acc[mi][ni], ra_l[mi], rb_h[ni]);
    }
}

__device__ __forceinline__ void zero_acc(float acc[4][4][4]) {
#pragma unroll
    for (int mi = 0; mi < 4; ++mi)
#pragma unroll
        for (int ni = 0; ni < 4; ++ni)
#pragma unroll
            for (int u = 0; u < 4; ++u) acc[mi][ni][u] = 0.0f;
}

// load one prepped 128x128 weight (hi+lo) into smem tiles with SROW stride
__device__ __forceinline__ void load_weight_smem(int p, int tid,
                                                 __nv_bfloat16* wh, __nv_bfloat16* wl) {
    const __nv_bfloat16* sh = g_wh + p * 16384;
    const __nv_bfloat16* sl = g_wl + p * 16384;
#pragma unroll
    for (int it = 0; it < 8; ++it) {
        int h = it * 2048 + tid * 8;
        int r = h >> 7, kk = h & 127;
        *(uint4*)(wh + r * SROW + kk) = *(const uint4*)(sh + h);
        *(uint4*)(wl + r * SROW + kk) = *(const uint4*)(sl + h);
    }
}

// ---------------- kernel 1: weight prep (split + transpose) ----------------
__global__ void k_prep(const float* Wa, const float* Wga, const float* Wb,
                       const float* Wgb, const float* Wg, const float* Wo) {
    int idx = blockIdx.x * 256 + threadIdx.x;   // 0 .. 6*16384-1
    const float* srcs[6] = {Wa, Wga, Wb, Wgb, Wg, Wo};
    int w = idx >> 14;
    int r = idx & 16383;
    int m = r >> 7;    // output channel
    int k = r & 127;   // input channel
    float v = srcs[w][k * 128 + m];   // transposed: Wt[m][k] = W[k][m]
    __nv_bfloat16 hi = __float2bfloat16(v);
    __nv_bfloat16 lo = __float2bfloat16(v - __bfloat162float(hi));
    g_wh[idx] = hi;
    g_wl[idx] = lo;
}

// ---------------- kernel 2: LN1 + 5 projections ----------------
__global__ void __launch_bounds__(256, 1) k_proj(
    const float* __restrict__ z,
    const float* __restrict__ g1, const float* __restrict__ b1,
    const float* __restrict__ ba, const float* __restrict__ bga,
    const float* __restrict__ bb, const float* __restrict__ bgb,
    const float* __restrict__ bg)
{
    extern __shared__ __nv_bfloat16 sm[];
    __nv_bfloat16* znh = sm;
    __nv_bfloat16* znl = sm + 128 * SROW;
    __nv_bfloat16* wh  = sm + 2 * 128 * SROW;
    __nv_bfloat16* wl  = sm + 3 * 128 * SROW;

    int tid = threadIdx.x, lane = tid & 31, warp = tid >> 5;
    int g = lane >> 2, tig = lane & 3;
    int wm = (warp >> 2) * 64;      // channel offset
    int wn = (warp & 3) * 32;       // token offset
    size_t t0 = (size_t)blockIdx.x * 128;

    // ---- LN1: each warp handles 16 token rows ----
    float gv[4], bv[4];
#pragma unroll
    for (int u = 0; u < 4; ++u) { gv[u] = g1[lane + 32 * u]; bv[u] = b1[lane + 32 * u]; }
    for (int rr = 0; rr < 16; ++rr) {
        int r = warp * 16 + rr;
        const float* zr = z + (t0 + r) * 128;
        float x[4], s = 0.f, ss = 0.f;
#pragma unroll
        for (int u = 0; u < 4; ++u) { x[u] = zr[lane + 32 * u]; s += x[u]; ss += x[u] * x[u]; }
#pragma unroll
        for (int o = 16; o > 0; o >>= 1) {
            s  += __shfl_xor_sync(0xFFFFFFFFu, s, o);
            ss += __shfl_xor_sync(0xFFFFFFFFu, ss, o);
        }
        float mean = s * (1.0f / 128.0f);
        float var  = ss * (1.0f / 128.0f) - mean * mean;
        float rstd = rsqrtf(var + LN_EPS);
#pragma unroll
        for (int u = 0; u < 4; ++u) {
            float v = (x[u] - mean) * rstd * gv[u] + bv[u];
            __nv_bfloat16 hi = __float2bfloat16(v);
            __nv_bfloat16 lo = __float2bfloat16(v - __bfloat162float(hi));
            znh[r * SROW + lane + 32 * u] = hi;
            znl[r * SROW + lane + 32 * u] = lo;
        }
    }

    float acc[4][4][4];
    float sva[4][4][4];

    // ---- P0: zn @ Wa + ba -> sva ----
    load_weight_smem(0, tid, wh, wl);
    __syncthreads();
    zero_acc(acc);
    gemm_tile(wh, wl, znh, znl, acc, g, tig, wm, wn, 8);
#pragma unroll
    for (int mi = 0; mi < 4; ++mi) {
        int c0 = wm + mi * 16 + g;
        float bz0 = ba[c0], bz1 = ba[c0 + 8];
#pragma unroll
        for (int ni = 0; ni < 4; ++ni) {
            sva[mi][ni][0] = acc[mi][ni][0] + bz0;
            sva[mi][ni][1] = acc[mi][ni][1] + bz0;
            sva[mi][ni][2] = acc[mi][ni][2] + bz1;
            sva[mi][ni][3] = acc[mi][ni][3] + bz1;
        }
    }

    // ---- P1: zn @ Wga + bga; a = sva * sigmoid(.) -> g_ah/g_al (channel-major) ----
    __syncthreads();
    load_weight_smem(1, tid, wh, wl);
    __syncthreads();
    zero_acc(acc);
    gemm_tile(wh, wl, znh, znl, acc, g, tig, wm, wn, 8);
#pragma unroll
    for (int mi = 0; mi < 4; ++mi) {
        int c0 = wm + mi * 16 + g, c1 = c0 + 8;
        float q0 = bga[c0], q1 = bga[c1];
#pragma unroll
        for (int ni = 0; ni < 4; ++ni) {
            size_t t = t0 + wn + ni * 8 + tig * 2;
            float v00 = sva[mi][ni][0] * sigm(acc[mi][ni][0] + q0);
            float v01 = sva[mi][ni][1] * sigm(acc[mi][ni][1] + q0);
            float v10 = sva[mi][ni][2] * sigm(acc[mi][ni][2] + q1);
            float v11 = sva[mi][ni][3] * sigm(acc[mi][ni][3] + q1);
            store_split2(g_ah, g_al, (size_t)c0 * NTOK + t, v00, v01);
            store_split2(g_ah, g_al, (size_t)c1 * NTOK + t, v10, v11);
        }
    }

    // ---- P2: zn @ Wb + bb -> sva ----
    __syncthreads();
    load_weight_smem(2, tid, wh, wl);
    __syncthreads();
    zero_acc(acc);
    gemm_tile(wh, wl, znh, znl, acc, g, tig, wm, wn, 8);
#pragma unroll
    for (int mi = 0; mi < 4; ++mi) {
        int c0 = wm + mi * 16 + g;
        float bz0 = bb[c0], bz1 = bb[c0 + 8];
#pragma unroll
        for (int ni = 0; ni < 4; ++ni) {
            sva[mi][ni][0] = acc[mi][ni][0] + bz0;
            sva[mi][ni][1] = acc[mi][ni][1] + bz0;
            sva[mi][ni][2] = acc[mi][ni][2] + bz1;
            sva[mi][ni][3] = acc[mi][ni][3] + bz1;
        }
    }

    // ---- P3: zn @ Wgb + bgb; b = sva * sigmoid(.) -> g_bh/g_bl ----
    __syncthreads();
    load_weight_smem(3, tid, wh, wl);
    __syncthreads();
    zero_acc(acc);
    gemm_tile(wh, wl, znh, znl, acc, g, tig, wm, wn, 8);
#pragma unroll
    for (int mi = 0; mi < 4; ++mi) {
        int c0 = wm + mi * 16 + g, c1 = c0 + 8;
        float q0 = bgb[c0], q1 = bgb[c1];
#pragma unroll
        for (int ni = 0; ni < 4; ++ni) {
            size_t t = t0 + wn + ni * 8 + tig * 2;
            float v00 = sva[mi][ni][0] * sigm(acc[mi][ni][0] + q0);
            float v01 = sva[mi][ni][1] * sigm(acc[mi][ni][1] + q0);
            float v10 = sva[mi][ni][2] * sigm(acc[mi][ni][2] + q1);
            float v11 = sva[mi][ni][3] * sigm(acc[mi][ni][3] + q1);
            store_split2(g_bh, g_bl, (size_t)c0 * NTOK + t, v00, v01);
            store_split2(g_bh, g_bl, (size_t)c1 * NTOK + t, v10, v11);
        }
    }

    // ---- P4: gate = sigmoid(zn @ Wg + bg) -> g_gate (channel-major fp32) ----
    __syncthreads();
    load_weight_smem(4, tid, wh, wl);
    __syncthreads();
    zero_acc(acc);
    gemm_tile(wh, wl, znh, znl, acc, g, tig, wm, wn, 8);
#pragma unroll
    for (int mi = 0; mi < 4; ++mi) {
        int c0 = wm + mi * 16 + g, c1 = c0 + 8;
        float q0 = bg[c0], q1 = bg[c1];
#pragma unroll
        for (int ni = 0; ni < 4; ++ni) {
            size_t t = t0 + wn + ni * 8 + tig * 2;
            float2 v0 = make_float2(sigm(acc[mi][ni][0] + q0), sigm(acc[mi][ni][1] + q0));
            float2 v1 = make_float2(sigm(acc[mi][ni][2] + q1), sigm(acc[mi][ni][3] + q1));
            *(float2*)(g_gate + (size_t)c0 * NTOK + t) = v0;
            *(float2*)(g_gate + (size_t)c1 * NTOK + t) = v1;
        }
    }
}

// ---------------- kernel 3: triangle einsum (per-channel GEMM A @ B^T) ----------------
__global__ void __launch_bounds__(256, 1) k_tri()
{
    extern __shared__ __nv_bfloat16 sm[];
    __nv_bfloat16* ah = sm;
    __nv_bfloat16* al = sm + 128 * SROW;
    __nv_bfloat16* bh = sm + 2 * 128 * SROW;
    __nv_bfloat16* bl = sm + 3 * 128 * SROW;

    int tid = threadIdx.x, lane = tid & 31, warp = tid >> 5;
    int g = lane >> 2, tig = lane & 3;
    int wm = (warp >> 2) * 64;
    int wn = (warp & 3) * 32;

    int c    = blockIdx.x / 9;     // tile index fastest -> same-c blocks co-resident
    int tile = blockIdx.x % 9;
    int i0 = (tile / 3) * 128;
    int j0 = (tile % 3) * 128;
    size_t baseA = (size_t)c * NTOK + (size_t)i0 * NSEQ;
    size_t baseB = (size_t)c * NTOK + (size_t)j0 * NSEQ;

    float acc[4][4][4];
    zero_acc(acc);

    for (int kc = 0; kc < 3; ++kc) {
#pragma unroll
        for (int it = 0; it < 8; ++it) {
            int h = it * 2048 + tid * 8;
            int r = h >> 7, kk = h & 127;
            size_t ga = baseA + (size_t)r * NSEQ + kc * 128 + kk;
            size_t gb = baseB + (size_t)r * NSEQ + kc * 128 + kk;
            *(uint4*)(ah + r * SROW + kk) = *(const uint4*)(g_ah + ga);
            *(uint4*)(al + r * SROW + kk) = *(const uint4*)(g_al + ga);
            *(uint4*)(bh + r * SROW + kk) = *(const uint4*)(g_bh + gb);
            *(uint4*)(bl + r * SROW + kk) = *(const uint4*)(g_bl + gb);
        }
        __syncthreads();
        gemm_tile(ah, al, bh, bl, acc, g, tig, wm, wn, 8);
        __syncthreads();
    }

    // write o channel-major fp32
#pragma unroll
    for (int mi = 0; mi < 4; ++mi) {
#pragma unroll
        for (int ni = 0; ni < 4; ++ni) {
            int r0  = i0 + wm + mi * 16 + g;
            int col = j0 + wn + ni * 8 + tig * 2;
            size_t off = (size_t)c * NTOK + (size_t)r0 * NSEQ + col;
            *(float2*)(g_o + off)            = make_float2(acc[mi][ni][0], acc[mi][ni][1]);
            *(float2*)(g_o + off + 8 * NSEQ) = make_float2(acc[mi][ni][2], acc[mi][ni][3]);
        }
    }
}

// ---------------- kernel 4: gather + LN2 + @Wo + gate ----------------
__global__ void __launch_bounds__(256, 1) k_out(
    const float* __restrict__ g2, const float* __restrict__ b2,
    const float* __restrict__ bo, float* __restrict__ out)
{
    extern __shared__ char smraw[];
    float* ot = (float*)smraw;                                      // 128 x 129 fp32
    __nv_bfloat16* onh = (__nv_bfloat16*)(smraw + 128 * 129 * 4);
    __nv_bfloat16* onl = onh + 128 * SROW;
    __nv_bfloat16* wh  = onl + 128 * SROW;
    __nv_bfloat16* wl  = wh + 128 * SROW;

    int tid = threadIdx.x, lane = tid & 31, warp = tid >> 5;
    int g = lane >> 2, tig = lane & 3;
    int wm = (warp >> 2) * 64;
    int wn = (warp & 3) * 32;
    size_t t0 = (size_t)blockIdx.x * 128;

    // gather o[c][t0..t0+127] -> ot[t][c] (coalesced reads, conflict-free smem writes)
#pragma unroll
    for (int it = 0; it < 64; ++it) {
        int idx = it * 256 + tid;
        int c  = idx >> 7;
        int tt = idx & 127;
        ot[tt * 129 + c] = g_o[(size_t)c * NTOK + t0 + tt];
    }
    __syncthreads();

    // LN2 per token row
    float gv[4], bv[4];
#pragma unroll
    for (int u = 0; u < 4; ++u) { gv[u] = g2[lane + 32 * u]; bv[u] = b2[lane + 32 * u]; }
    for (int rr = 0; rr < 16; ++rr) {
        int r = warp * 16 + rr;
        float x[4], s = 0.f, ss = 0.f;
#pragma unroll
        for (int u = 0; u < 4; ++u) {
            x[u] = ot[r * 129 + lane + 32 * u];
            s += x[u]; ss += x[u] * x[u];
        }
#pragma unroll
        for (int o = 16; o > 0; o >>= 1) {
            s  += __shfl_xor_sync(0xFFFFFFFFu, s, o);
            ss += __shfl_xor_sync(0xFFFFFFFFu, ss, o);
        }
        float mean = s * (1.0f / 128.0f);
        float var  = ss * (1.0f / 128.0f) - mean * mean;
        float rstd = rsqrtf(var + LN_EPS);
#pragma unroll
        for (int u = 0; u < 4; ++u) {
            float v = (x[u] - mean) * rstd * gv[u] + bv[u];
            __nv_bfloat16 hi = __float2bfloat16(v);
            __nv_bfloat16 lo = __float2bfloat16(v - __bfloat162float(hi));
            onh[r * SROW + lane + 32 * u] = hi;
            onl[r * SROW + lane + 32 * u] = lo;
        }
    }

    load_weight_smem(5, tid, wh, wl);   // Wo
    __syncthreads();

    float acc[4][4][4];
    zero_acc(acc);
    gemm_tile(wh, wl, onh, onl, acc, g, tig, wm, wn, 8);

    // epilogue: out[t][c] = gate[c][t] * (acc + bo[c])
#pragma unroll
    for (int mi = 0; mi < 4; ++mi) {
        int c0 = wm + mi * 16 + g, c1 = c0 + 8;
        float q0 = bo[c0], q1 = bo[c1];
#pragma unroll
        for (int ni = 0; ni < 4; ++ni) {
            size_t t = t0 + wn + ni * 8 + tig * 2;
            float2 gt0 = *(const float2*)(g_gate + (size_t)c0 * NTOK + t);
            float2 gt1 = *(const float2*)(g_gate + (size_t)c1 * NTOK + t);
            out[t * 128 + c0]       = gt0.x * (acc[mi][ni][0] + q0);
            out[(t + 1) * 128 + c0] = gt0.y * (acc[mi][ni][1] + q0);
            out[t * 128 + c1]       = gt1.x * (acc[mi][ni][2] + q1);
            out[(t + 1) * 128 + c1] = gt1.y * (acc[mi][ni][3] + q1);
        }
    }
}

// ---------------- launch ----------------
extern "C" void kernel_launch(void* const* d_in, const int* in_sizes, int n_in,
                              void* d_out, int out_size)
{
    const float* z    = (const float*)d_in[0];
    const float* ln1g = (const float*)d_in[1];
    const float* ln1b = (const float*)d_in[2];
    const float* ln2g = (const float*)d_in[3];
    const float* ln2b = (const float*)d_in[4];
    const float* Wa   = (const float*)d_in[5];
    const float* ba   = (const float*)d_in[6];
    const float* Wga  = (const float*)d_in[7];
    const float* bga  = (const float*)d_in[8];
    const float* Wb   = (const float*)d_in[9];
    const float* bb   = (const float*)d_in[10];
    const float* Wgb  = (const float*)d_in[11];
    const float* bgb  = (const float*)d_in[12];
    const float* Wg   = (const float*)d_in[13];
    const float* bg   = (const float*)d_in[14];
    const float* Wo   = (const float*)d_in[15];
    const float* bo   = (const float*)d_in[16];

    const int smA = 4 * 128 * SROW * 2;                 // 139264 B
    const int smO = 128 * 129 * 4 + 4 * 128 * SROW * 2; // 205312 B
    cudaFuncSetAttribute(k_proj, cudaFuncAttributeMaxDynamicSharedMemorySize, smA);
    cudaFuncSetAttribute(k_tri,  cudaFuncAttributeMaxDynamicSharedMemorySize, smA);
    cudaFuncSetAttribute(k_out,  cudaFuncAttributeMaxDynamicSharedMemorySize, smO);

    k_prep<<<384, 256>>>(Wa, Wga, Wb, Wgb, Wg, Wo);
    k_proj<<<1152, 256, smA>>>(z, ln1g, ln1b, ba, bga, bb, bgb, bg);
    k_tri<<<1152, 256, smA>>>();
    k_out<<<1152, 256, smO>>>(ln2g, ln2b, bo, (float*)d_out);
}

// round 17
// speedup vs baseline: 1.2261x; 1.2243x over previous
#include <cuda_runtime.h>
#include <cuda_bf16.h>
#include <stdint.h>

#define NSEQ 384
#define NTOK 147456            // 384*384
#define CDIM 128
#define SROW 136               // smem row stride (halves), 128x128 tiles: conflict-free
#define SROW2 72               // smem row stride (halves), 128x64 tiles: conflict-free
#define LN_EPS 1e-5f

// ---------------- scratch (device globals: allocation-free) ----------------
__device__ __align__(16) __nv_bfloat16 g_ah[(size_t)CDIM * NTOK];
__device__ __align__(16) __nv_bfloat16 g_al[(size_t)CDIM * NTOK];
__device__ __align__(16) __nv_bfloat16 g_bh[(size_t)CDIM * NTOK];
__device__ __align__(16) __nv_bfloat16 g_bl[(size_t)CDIM * NTOK];
__device__ __align__(16) float         g_gate[(size_t)CDIM * NTOK];
__device__ __align__(16) float         g_o[(size_t)CDIM * NTOK];
__device__ __align__(16) __nv_bfloat16 g_wh[6 * 16384];
__device__ __align__(16) __nv_bfloat16 g_wl[6 * 16384];

// ---------------- helpers ----------------
__device__ __forceinline__ uint32_t cvta_s(const void* p) {
    return (uint32_t)__cvta_generic_to_shared(p);
}

__device__ __forceinline__ void ldsm4(uint32_t* r, uint32_t addr) {
    asm volatile("ldmatrix.sync.aligned.m8n8.x4.shared.b16 {%0,%1,%2,%3}, [%4];\n"
                 : "=r"(r[0]), "=r"(r[1]), "=r"(r[2]), "=r"(r[3]) : "r"(addr));
}

__device__ __forceinline__ void mma16816(float* c, const uint32_t* a, const uint32_t* b) {
    asm volatile(
        "mma.sync.aligned.m16n8k16.row.col.f32.bf16.bf16.f32 "
        "{%0,%1,%2,%3}, {%4,%5,%6,%7}, {%8,%9}, {%0,%1,%2,%3};\n"
        : "+f"(c[0]), "+f"(c[1]), "+f"(c[2]), "+f"(c[3])
        : "r"(a[0]), "r"(a[1]), "r"(a[2]), "r"(a[3]), "r"(b[0]), "r"(b[1]));
}

__device__ __forceinline__ void cpa16(uint32_t dst, const void* src) {
    asm volatile("cp.async.cg.shared.global [%0], [%1], 16;\n" :: "r"(dst), "l"(src));
}
#define CP_COMMIT()  asm volatile("cp.async.commit_group;\n")
#define CP_WAIT(n)   asm volatile("cp.async.wait_group %0;\n" :: "n"(n))

__device__ __forceinline__ float sigm(float x) { return 1.0f / (1.0f + __expf(-x)); }

__device__ __forceinline__ void store_split2(__nv_bfloat16* H, __nv_bfloat16* L,
                                             size_t off, float v0, float v1) {
    __nv_bfloat16 h0 = __float2bfloat16(v0);
    __nv_bfloat16 h1 = __float2bfloat16(v1);
    __nv_bfloat16 l0 = __float2bfloat16(v0 - __bfloat162float(h0));
    __nv_bfloat16 l1 = __float2bfloat16(v1 - __bfloat162float(h1));
    __nv_bfloat162 hh; hh.x = h0; hh.y = h1;
    __nv_bfloat162 ll; ll.x = l0; ll.y = l1;
    *(__nv_bfloat162*)(H + off) = hh;
    *(__nv_bfloat162*)(L + off) = ll;
}

__device__ __forceinline__ void zero_acc(float acc[2][4][4]) {
#pragma unroll
    for (int mi = 0; mi < 2; ++mi)
#pragma unroll
        for (int ni = 0; ni < 4; ++ni)
#pragma unroll
            for (int u = 0; u < 4; ++u) acc[mi][ni][u] = 0.0f;
}

// 32x32 warp tile over a 128x128 (or 128x64-chunk) GEMM, bf16x3 split precision.
// A: [m rows x k] stride srow; B: [n rows x k] stride srow. ldmatrix fragments.
__device__ __forceinline__ void gemm32(
    const __nv_bfloat16* Ah, const __nv_bfloat16* Al,
    const __nv_bfloat16* Bh, const __nv_bfloat16* Bl,
    float acc[2][4][4], int lane, int wm, int wn, int srow, int nk)
{
    uint32_t bAh = cvta_s(Ah), bAl = cvta_s(Al);
    uint32_t bBh = cvta_s(Bh), bBl = cvta_s(Bl);
    int rowA = lane & 15;
    int kA   = ((lane >> 4) & 1) << 3;
    int rB   = lane & 7;
    int kB   = ((lane >> 3) & 1) << 3;
    int nB   = ((lane >> 4) & 1) << 3;

#pragma unroll
    for (int ks = 0; ks < 8; ++ks) {
        if (ks >= nk) break;
        int k0 = ks * 16;
        uint32_t ra_h[2][4], ra_l[2][4], rb_h[2][4], rb_l[2][4];
#pragma unroll
        for (int mi = 0; mi < 2; ++mi) {
            uint32_t off = (uint32_t)(((wm + mi * 16 + rowA) * srow + k0 + kA) << 1);
            ldsm4(ra_h[mi], bAh + off);
            ldsm4(ra_l[mi], bAl + off);
        }
#pragma unroll
        for (int p = 0; p < 2; ++p) {
            uint32_t off = (uint32_t)(((wn + p * 16 + nB + rB) * srow + k0 + kB) << 1);
            ldsm4(rb_h[p], bBh + off);
            ldsm4(rb_l[p], bBl + off);
        }
#pragma unroll
        for (int mi = 0; mi < 2; ++mi)
#pragma unroll
            for (int ni = 0; ni < 4; ++ni)
                mma16816(acc[mi][ni], ra_h[mi], &rb_h[ni >> 1][(ni & 1) * 2]);
#pragma unroll
        for (int mi = 0; mi < 2; ++mi)
#pragma unroll
            for (int ni = 0; ni < 4; ++ni)
                mma16816(acc[mi][ni], ra_h[mi], &rb_l[ni >> 1][(ni & 1) * 2]);
#pragma unroll
        for (int mi = 0; mi < 2; ++mi)
#pragma unroll
            for (int ni = 0; ni < 4; ++ni)
                mma16816(acc[mi][ni], ra_l[mi], &rb_h[ni >> 1][(ni & 1) * 2]);
    }
}

// async-load prepped weight p (hi+lo planes) into smem tile pair (stride SROW)
__device__ __forceinline__ void w_load_async(int p, int tid, __nv_bfloat16* wh,
                                             __nv_bfloat16* wl) {
    uint32_t dh = cvta_s(wh), dl = cvta_s(wl);
    const __nv_bfloat16* sh = g_wh + p * 16384;
    const __nv_bfloat16* sl = g_wl + p * 16384;
#pragma unroll
    for (int it = 0; it < 4; ++it) {
        int idx = it * 512 + tid;          // 2048 chunks of 16B per plane
        int r = idx >> 4, c16 = idx & 15;
        uint32_t so = (uint32_t)((r * SROW + c16 * 8) << 1);
        int go = r * 128 + c16 * 8;
        cpa16(dh + so, sh + go);
        cpa16(dl + so, sl + go);
    }
}

// ---------------- kernel 1: weight prep (split + transpose) ----------------
__global__ void k_prep(const float* Wa, const float* Wga, const float* Wb,
                       const float* Wgb, const float* Wg, const float* Wo) {
    int idx = blockIdx.x * 256 + threadIdx.x;   // 0 .. 6*16384-1
    const float* srcs[6] = {Wa, Wga, Wb, Wgb, Wg, Wo};
    int w = idx >> 14;
    int r = idx & 16383;
    int m = r >> 7;
    int k = r & 127;
    float v = srcs[w][k * 128 + m];             // transpose: Wt[m][k] = W[k][m]
    __nv_bfloat16 hi = __float2bfloat16(v);
    __nv_bfloat16 lo = __float2bfloat16(v - __bfloat162float(hi));
    g_wh[idx] = hi;
    g_wl[idx] = lo;
}

// ---------------- kernel 2: LN1 + 5 projections ----------------
__global__ void __launch_bounds__(512, 1) k_proj(
    const float* __restrict__ z,
    const float* __restrict__ g1, const float* __restrict__ b1,
    const float* __restrict__ ba, const float* __restrict__ bga,
    const float* __restrict__ bb, const float* __restrict__ bgb,
    const float* __restrict__ bg)
{
    extern __shared__ char smraw[];
    __nv_bfloat16* znh = (__nv_bfloat16*)smraw;                       // 34816 B
    __nv_bfloat16* znl = (__nv_bfloat16*)(smraw + 34816);
    __nv_bfloat16* wbh[2] = {(__nv_bfloat16*)(smraw + 69632),
                             (__nv_bfloat16*)(smraw + 139264)};
    __nv_bfloat16* wbl[2] = {(__nv_bfloat16*)(smraw + 104448),
                             (__nv_bfloat16*)(smraw + 174080)};

    int tid = threadIdx.x, lane = tid & 31, warp = tid >> 5;
    int g = lane >> 2, tig = lane & 3;
    int wm = (warp >> 2) * 32;
    int wn = (warp & 3) * 32;
    size_t t0 = (size_t)blockIdx.x * 128;

    // prefetch weight 0
    w_load_async(0, tid, wbh[0], wbl[0]);
    CP_COMMIT();

    // ---- LN1: each warp handles 8 token rows ----
    float gv[4], bv[4];
#pragma unroll
    for (int u = 0; u < 4; ++u) { gv[u] = g1[lane + 32 * u]; bv[u] = b1[lane + 32 * u]; }
    for (int rr = 0; rr < 8; ++rr) {
        int r = warp * 8 + rr;
        const float* zr = z + (t0 + r) * 128;
        float x[4], s = 0.f, ss = 0.f;
#pragma unroll
        for (int u = 0; u < 4; ++u) { x[u] = zr[lane + 32 * u]; s += x[u]; ss += x[u] * x[u]; }
#pragma unroll
        for (int o = 16; o > 0; o >>= 1) {
            s  += __shfl_xor_sync(0xFFFFFFFFu, s, o);
            ss += __shfl_xor_sync(0xFFFFFFFFu, ss, o);
        }
        float mean = s * (1.0f / 128.0f);
        float var  = ss * (1.0f / 128.0f) - mean * mean;
        float rstd = rsqrtf(var + LN_EPS);
#pragma unroll
        for (int u = 0; u < 4; ++u) {
            float v = (x[u] - mean) * rstd * gv[u] + bv[u];
            __nv_bfloat16 hi = __float2bfloat16(v);
            __nv_bfloat16 lo = __float2bfloat16(v - __bfloat162float(hi));
            znh[r * SROW + lane + 32 * u] = hi;
            znl[r * SROW + lane + 32 * u] = lo;
        }
    }

    float acc[2][4][4];
    float sva[2][4][4];

#pragma unroll
    for (int p = 0; p < 5; ++p) {
        if (p < 4) { w_load_async(p + 1, tid, wbh[(p + 1) & 1], wbl[(p + 1) & 1]); CP_COMMIT(); }
        if (p < 4) CP_WAIT(1); else CP_WAIT(0);
        __syncthreads();

        zero_acc(acc);
        gemm32(wbh[p & 1], wbl[p & 1], znh, znl, acc, lane, wm, wn, SROW, 8);

        if (p == 0 || p == 2) {                  // zn@Wa+ba / zn@Wb+bb -> sva
            const float* bias = (p == 0) ? ba : bb;
#pragma unroll
            for (int mi = 0; mi < 2; ++mi) {
                int c0 = wm + mi * 16 + g;
                float q0 = bias[c0], q1 = bias[c0 + 8];
#pragma unroll
                for (int ni = 0; ni < 4; ++ni) {
                    sva[mi][ni][0] = acc[mi][ni][0] + q0;
                    sva[mi][ni][1] = acc[mi][ni][1] + q0;
                    sva[mi][ni][2] = acc[mi][ni][2] + q1;
                    sva[mi][ni][3] = acc[mi][ni][3] + q1;
                }
            }
        } else if (p == 1 || p == 3) {           // gated product -> g_a / g_b
            const float* bias = (p == 1) ? bga : bgb;
            __nv_bfloat16* H = (p == 1) ? g_ah : g_bh;
            __nv_bfloat16* L = (p == 1) ? g_al : g_bl;
#pragma unroll
            for (int mi = 0; mi < 2; ++mi) {
                int c0 = wm + mi * 16 + g, c1 = c0 + 8;
                float q0 = bias[c0], q1 = bias[c1];
#pragma unroll
                for (int ni = 0; ni < 4; ++ni) {
                    size_t t = t0 + wn + ni * 8 + tig * 2;
                    float v00 = sva[mi][ni][0] * sigm(acc[mi][ni][0] + q0);
                    float v01 = sva[mi][ni][1] * sigm(acc[mi][ni][1] + q0);
                    float v10 = sva[mi][ni][2] * sigm(acc[mi][ni][2] + q1);
                    float v11 = sva[mi][ni][3] * sigm(acc[mi][ni][3] + q1);
                    store_split2(H, L, (size_t)c0 * NTOK + t, v00, v01);
                    store_split2(H, L, (size_t)c1 * NTOK + t, v10, v11);
                }
            }
        } else {                                 // gate -> g_gate fp32
#pragma unroll
            for (int mi = 0; mi < 2; ++mi) {
                int c0 = wm + mi * 16 + g, c1 = c0 + 8;
                float q0 = bg[c0], q1 = bg[c1];
#pragma unroll
                for (int ni = 0; ni < 4; ++ni) {
                    size_t t = t0 + wn + ni * 8 + tig * 2;
                    *(float2*)(g_gate + (size_t)c0 * NTOK + t) =
                        make_float2(sigm(acc[mi][ni][0] + q0), sigm(acc[mi][ni][1] + q0));
                    *(float2*)(g_gate + (size_t)c1 * NTOK + t) =
                        make_float2(sigm(acc[mi][ni][2] + q1), sigm(acc[mi][ni][3] + q1));
                }
            }
        }
        __syncthreads();   // buffer-reuse guard
    }
}

// ---------------- kernel 3: triangle einsum, cp.async double-buffered ----------------
__global__ void __launch_bounds__(512, 1) k_tri()
{
    extern __shared__ char smraw[];
    // stage s: ah @ s*73728, al +18432, bh +36864, bl +55296 (bytes)
    int tid = threadIdx.x, lane = tid & 31, warp = tid >> 5;
    int wm = (warp >> 2) * 32;
    int wn = (warp & 3) * 32;

    int c    = blockIdx.x / 9;      // tile index fastest -> same-c co-resident in L2
    int tile = blockIdx.x % 9;
    int i0 = (tile / 3) * 128;
    int j0 = (tile % 3) * 128;
    size_t baseA = (size_t)c * NTOK + (size_t)i0 * NSEQ;
    size_t baseB = (size_t)c * NTOK + (size_t)j0 * NSEQ;

    uint32_t sbase = cvta_s(smraw);

    // chunk loader: 4 tiles x 128 rows x 64 halves, 16B per cp.async
    auto load_chunk = [&](int kc, int s) {
        uint32_t stg = sbase + (uint32_t)s * 73728u;
        const __nv_bfloat16* gsrc[4] = {g_ah + baseA, g_al + baseA,
                                        g_bh + baseB, g_bl + baseB};
#pragma unroll
        for (int it = 0; it < 8; ++it) {
            int idx = it * 512 + tid;          // 4096 chunks
            int t4 = idx >> 10;
            int r  = (idx >> 3) & 127;
            int c8 = idx & 7;
            uint32_t dst = stg + (uint32_t)t4 * 18432u +
                           (uint32_t)((r * SROW2 + c8 * 8) << 1);
            cpa16(dst, gsrc[t4] + (size_t)r * NSEQ + kc * 64 + c8 * 8);
        }
    };

    float acc[2][4][4];
    zero_acc(acc);

    load_chunk(0, 0);
    CP_COMMIT();
#pragma unroll 1
    for (int kc = 0; kc < 6; ++kc) {
        if (kc < 5) { load_chunk(kc + 1, (kc + 1) & 1); CP_COMMIT(); }
        if (kc < 5) CP_WAIT(1); else CP_WAIT(0);
        __syncthreads();
        const char* stg = smraw + (size_t)(kc & 1) * 73728;
        gemm32((const __nv_bfloat16*)(stg),
               (const __nv_bfloat16*)(stg + 18432),
               (const __nv_bfloat16*)(stg + 36864),
               (const __nv_bfloat16*)(stg + 55296),
               acc, lane, wm, wn, SROW2, 4);
        __syncthreads();
    }

    // write o channel-major fp32 (32B/quad, sector-complete)
    int g = lane >> 2, tig = lane & 3;
#pragma unroll
    for (int mi = 0; mi < 2; ++mi) {
#pragma unroll
        for (int ni = 0; ni < 4; ++ni) {
            int r0  = i0 + wm + mi * 16 + g;
            int col = j0 + wn + ni * 8 + tig * 2;
            size_t off = (size_t)c * NTOK + (size_t)r0 * NSEQ + col;
            *(float2*)(g_o + off)            = make_float2(acc[mi][ni][0], acc[mi][ni][1]);
            *(float2*)(g_o + off + 8 * NSEQ) = make_float2(acc[mi][ni][2], acc[mi][ni][3]);
        }
    }
}

// ---------------- kernel 4: gather + LN2 + @Wo + gate, smem-transposed epilogue ----------------
__global__ void __launch_bounds__(512, 1) k_out(
    const float* __restrict__ g2, const float* __restrict__ b2,
    const float* __restrict__ bo, float* __restrict__ out)
{
    extern __shared__ char smraw[];
    float* ot = (float*)smraw;                                   // 128 x 132 fp32 = 67584 B
    __nv_bfloat16* onh = (__nv_bfloat16*)(smraw + 67584);
    __nv_bfloat16* onl = (__nv_bfloat16*)(smraw + 102400);
    __nv_bfloat16* wh  = (__nv_bfloat16*)(smraw + 137216);
    __nv_bfloat16* wl  = (__nv_bfloat16*)(smraw + 172032);

    int tid = threadIdx.x, lane = tid & 31, warp = tid >> 5;
    int g = lane >> 2, tig = lane & 3;
    int wm = (warp >> 2) * 32;
    int wn = (warp & 3) * 32;
    size_t t0 = (size_t)blockIdx.x * 128;

    w_load_async(5, tid, wh, wl);     // Wo
    CP_COMMIT();

    // gather o[c][t0..t0+127] -> ot[t][c] (coalesced reads)
#pragma unroll
    for (int it = 0; it < 32; ++it) {
        int idx = it * 512 + tid;
        int c  = idx >> 7;
        int tt = idx & 127;
        ot[tt * 132 + c] = g_o[(size_t)c * NTOK + t0 + tt];
    }
    __syncthreads();

    // LN2 per token row (each warp 8 rows)
    float gv[4], bv[4];
#pragma unroll
    for (int u = 0; u < 4; ++u) { gv[u] = g2[lane + 32 * u]; bv[u] = b2[lane + 32 * u]; }
    for (int rr = 0; rr < 8; ++rr) {
        int r = warp * 8 + rr;
        float x[4], s = 0.f, ss = 0.f;
#pragma unroll
        for (int u = 0; u < 4; ++u) {
            x[u] = ot[r * 132 + lane + 32 * u];
            s += x[u]; ss += x[u] * x[u];
        }
#pragma unroll
        for (int o = 16; o > 0; o >>= 1) {
            s  += __shfl_xor_sync(0xFFFFFFFFu, s, o);
            ss += __shfl_xor_sync(0xFFFFFFFFu, ss, o);
        }
        float mean = s * (1.0f / 128.0f);
        float var  = ss * (1.0f / 128.0f) - mean * mean;
        float rstd = rsqrtf(var + LN_EPS);
#pragma unroll
        for (int u = 0; u < 4; ++u) {
            float v = (x[u] - mean) * rstd * gv[u] + bv[u];
            __nv_bfloat16 hi = __float2bfloat16(v);
            __nv_bfloat16 lo = __float2bfloat16(v - __bfloat162float(hi));
            onh[r * SROW + lane + 32 * u] = hi;
            onl[r * SROW + lane + 32 * u] = lo;
        }
    }

    CP_WAIT(0);
    __syncthreads();

    float acc[2][4][4];
    zero_acc(acc);
    gemm32(wh, wl, onh, onl, acc, lane, wm, wn, SROW, 8);

    // epilogue: gate * (acc + bo) -> ot[t][c] (conflict-free), then coalesced out
#pragma unroll
    for (int mi = 0; mi < 2; ++mi) {
        int c0 = wm + mi * 16 + g, c1 = c0 + 8;
        float q0 = bo[c0], q1 = bo[c1];
#pragma unroll
        for (int ni = 0; ni < 4; ++ni) {
            int tl = wn + ni * 8 + tig * 2;
            size_t t = t0 + tl;
            float2 gt0 = *(const float2*)(g_gate + (size_t)c0 * NTOK + t);
            float2 gt1 = *(const float2*)(g_gate + (size_t)c1 * NTOK + t);
            ot[tl * 132 + c0]       = gt0.x * (acc[mi][ni][0] + q0);
            ot[(tl + 1) * 132 + c0] = gt0.y * (acc[mi][ni][1] + q0);
            ot[tl * 132 + c1]       = gt1.x * (acc[mi][ni][2] + q1);
            ot[(tl + 1) * 132 + c1] = gt1.y * (acc[mi][ni][3] + q1);
        }
    }
    __syncthreads();

    // fully-coalesced float4 stores: one warp per token row per pass
#pragma unroll
    for (int it = 0; it < 8; ++it) {
        int idx = it * 512 + tid;          // 4096 float4 = 128 rows x 32
        int tt = idx >> 5;
        int cq = idx & 31;
        float4 v = *(const float4*)(ot + tt * 132 + cq * 4);
        *(float4*)(out + (t0 + tt) * 128 + cq * 4) = v;
    }
}

// ---------------- launch ----------------
extern "C" void kernel_launch(void* const* d_in, const int* in_sizes, int n_in,
                              void* d_out, int out_size)
{
    const float* z    = (const float*)d_in[0];
    const float* ln1g = (const float*)d_in[1];
    const float* ln1b = (const float*)d_in[2];
    const float* ln2g = (const float*)d_in[3];
    const float* ln2b = (const float*)d_in[4];
    const float* Wa   = (const float*)d_in[5];
    const float* ba   = (const float*)d_in[6];
    const float* Wga  = (const float*)d_in[7];
    const float* bga  = (const float*)d_in[8];
    const float* Wb   = (const float*)d_in[9];
    const float* bb   = (const float*)d_in[10];
    const float* Wgb  = (const float*)d_in[11];
    const float* bgb  = (const float*)d_in[12];
    const float* Wg   = (const float*)d_in[13];
    const float* bg   = (const float*)d_in[14];
    const float* Wo   = (const float*)d_in[15];
    const float* bo   = (const float*)d_in[16];

    const int smP = 208896;   // zn(69632) + 2 weight buffers (2*69632)
    const int smT = 147456;   // 2 stages x 4 tiles x 128x72 halves
    const int smO = 206848;   // ot(67584) + on(69632) + w(69632)
    cudaFuncSetAttribute(k_proj, cudaFuncAttributeMaxDynamicSharedMemorySize, smP);
    cudaFuncSetAttribute(k_tri,  cudaFuncAttributeMaxDynamicSharedMemorySize, smT);
    cudaFuncSetAttribute(k_out,  cudaFuncAttributeMaxDynamicSharedMemorySize, smO);

    k_prep<<<384, 256>>>(Wa, Wga, Wb, Wgb, Wg, Wo);
    k_proj<<<1152, 512, smP>>>(z, ln1g, ln1b, ba, bga, bb, bgb, bg);
    k_tri<<<1152, 512, smT>>>();
    k_out<<<1152, 512, smO>>>(ln2g, ln2b, bo, (float*)d_out);
}